// round 13
// baseline (speedup 1.0000x reference)
#include <cuda_runtime.h>
#include <cstdint>

// Fold: x (B=8, C=32, K1=8, K2=8, L=4096) -> out (B, C, H=260, W=260)
// kernel (8,8), stride (4,4), n = 64.
// R4 champion gather (minimal 322MB traffic, L2::256B reads) + smem-staged
// bulk store: each block's 256 output quads are contiguous 4KB in memory
// (tid-ordered quad map), so stage them in smem and emit ONE
// cp.async.bulk 1D store per block -> 4KB write bursts instead of 32x128B.

namespace {
constexpr int B = 8;
constexpr int C = 32;
constexpr int K = 8;
constexpr int N = 64;               // patch grid
constexpr int L = N * N;            // 4096
constexpr int H = 260;
constexpr int W = 260;
constexpr int QW = W / 4;           // 65 quads per row
constexpr int TOTAL_Q = B * C * H * QW;  // 4,326,400 = 16900 * 256 exactly
}

__device__ __forceinline__ float ldg_256(const float* p) {
    float v;
    asm volatile("ld.global.nc.L2::256B.f32 %0, [%1];" : "=f"(v) : "l"(p));
    return v;
}

__global__ __launch_bounds__(256) void fold_quad_bulk_kernel(
    const float* __restrict__ x, float* __restrict__ out) {
    __shared__ alignas(128) float4 stage[256];   // 4KB output tile

    int tid = blockIdx.x * 256 + threadIdx.x;    // grid exact, no tail

    int q  = tid % QW;          // 0..64
    int t  = tid / QW;
    int oh = t % H;             // 0..259
    int bc = t / H;             // 0..255

    const float* __restrict__ xb = x + (long long)bc * (K * K * L);

    int di0 = oh & 3;
    int di1 = di0 + 4;
    int i0  = oh >> 2;          // may be 64 (invalid) when oh >= 256
    int i1  = i0 - 1;           // may be -1 when oh < 4

    bool vi0 = i0 < N;
    bool vi1 = i1 >= 0;
    bool vj0 = q < N;
    bool vj1 = q >= 1;

    int row0 = i0 * N;
    int row1 = i1 * N;

    bool v00 = vi0 && vj0, v01 = vi0 && vj1;
    bool v10 = vi1 && vj0, v11 = vi1 && vj1;

    float a[4], b[4], c[4], d[4];
#pragma unroll
    for (int r = 0; r < 4; r++) {
        a[r] = v00 ? ldg_256(xb + (di0 * K + r) * L + row0 + q) : 0.f;
        b[r] = v01 ? ldg_256(xb + (di0 * K + r + 4) * L + row0 + q - 1) : 0.f;
        c[r] = v10 ? ldg_256(xb + (di1 * K + r) * L + row1 + q) : 0.f;
        d[r] = v11 ? ldg_256(xb + (di1 * K + r + 4) * L + row1 + q - 1) : 0.f;
    }

    float4 o;
    o.x = (a[0] + b[0]) + (c[0] + d[0]);
    o.y = (a[1] + b[1]) + (c[1] + d[1]);
    o.z = (a[2] + b[2]) + (c[2] + d[2]);
    o.w = (a[3] + b[3]) + (c[3] + d[3]);

    stage[threadIdx.x] = o;
    __syncthreads();

    if (threadIdx.x == 0) {
        // Block's 256 quads are output elements [blockIdx.x*1024,
        // blockIdx.x*1024 + 1024) — one contiguous 4KB chunk.
        float* gdst = out + (long long)blockIdx.x * 1024;
        uint32_t saddr;
        asm("{ .reg .u64 t; cvta.to.shared.u64 t, %1; cvt.u32.u64 %0, t; }"
            : "=r"(saddr) : "l"((const void*)stage));
        asm volatile("fence.proxy.async.shared::cta;" ::: "memory");
        asm volatile(
            "cp.async.bulk.global.shared::cta.bulk_group [%0], [%1], %2;"
            :: "l"(gdst), "r"(saddr), "n"(4096) : "memory");
        asm volatile("cp.async.bulk.commit_group;" ::: "memory");
        // Ensure smem reads complete before block exit / smem reuse.
        asm volatile("cp.async.bulk.wait_group.read 0;" ::: "memory");
    }
}

extern "C" void kernel_launch(void* const* d_in, const int* in_sizes, int n_in,
                              void* d_out, int out_size) {
    const float* x = (const float*)d_in[0];
    float* out = (float*)d_out;
    fold_quad_bulk_kernel<<<TOTAL_Q / 256, 256>>>(x, out);  // 16,900 blocks
}

// round 14
// speedup vs baseline: 1.0018x; 1.0018x over previous
#include <cuda_runtime.h>

// Fold: x (B=8, C=32, K1=8, K2=8, L=4096) -> out (B, C, H=260, W=260)
// kernel (8,8), stride (4,4), n = 64.
//
// FINAL KERNEL (R4 champion; best measured 48.99us kernel / 53.28us bench).
//
// Gather formulation: for output (oh, ow=4q+r), the contributing kernel
// offsets are di ∈ {oh&3, oh&3+4}, dj ∈ {r, r+4}, giving patch cols q and
// q-1. Every input element is read exactly once, every output written
// exactly once; both streams are tid-contiguous => 322MB minimum traffic.
// ld.global.nc.L2::256B promotes read granularity (each 256B plane-row is
// fully consumed). float4 stores.
//
// Verified at the HBM roofline: 80-83% DRAM pipe (~6.5TB/s on a 79/21
// read/write mix); interventions on L1 wavefronts, store policy (.cs and
// TMA bulk), MLP, occupancy, and index ALU were all neutral or negative.

namespace {
constexpr int B = 8;
constexpr int C = 32;
constexpr int K = 8;
constexpr int N = 64;               // patch grid
constexpr int L = N * N;            // 4096
constexpr int H = 260;
constexpr int W = 260;
constexpr int QW = W / 4;           // 65 quads per row
constexpr int TOTAL_Q = B * C * H * QW;  // 4,326,400 = 16900 * 256 exactly
}

__device__ __forceinline__ float ldg_256(const float* p) {
    float v;
    asm volatile("ld.global.nc.L2::256B.f32 %0, [%1];" : "=f"(v) : "l"(p));
    return v;
}

__global__ __launch_bounds__(256) void fold_quad_l2_kernel(
    const float* __restrict__ x, float* __restrict__ out) {
    int tid = blockIdx.x * blockDim.x + threadIdx.x;   // grid exact, no tail

    int q  = tid % QW;          // 0..64
    int t  = tid / QW;
    int oh = t % H;             // 0..259
    int bc = t / H;             // 0..255

    const float* __restrict__ xb = x + (long long)bc * (K * K * L);

    int di0 = oh & 3;
    int di1 = di0 + 4;
    int i0  = oh >> 2;          // row for di0 (may be 64 == invalid)
    int i1  = i0 - 1;           // row for di1 (may be -1)

    bool vi0 = i0 < N;
    bool vi1 = i1 >= 0;
    bool vj0 = q < N;           // q may be 64 on last quad
    bool vj1 = q >= 1;

    int row0 = i0 * N;
    int row1 = i1 * N;

    bool v00 = vi0 && vj0, v01 = vi0 && vj1;
    bool v10 = vi1 && vj0, v11 = vi1 && vj1;

    float a[4], b[4], c[4], d[4];
#pragma unroll
    for (int r = 0; r < 4; r++) {
        a[r] = v00 ? ldg_256(xb + (di0 * K + r) * L + row0 + q) : 0.f;
        b[r] = v01 ? ldg_256(xb + (di0 * K + r + 4) * L + row0 + q - 1) : 0.f;
        c[r] = v10 ? ldg_256(xb + (di1 * K + r) * L + row1 + q) : 0.f;
        d[r] = v11 ? ldg_256(xb + (di1 * K + r + 4) * L + row1 + q - 1) : 0.f;
    }

    float4 o;
    o.x = (a[0] + b[0]) + (c[0] + d[0]);
    o.y = (a[1] + b[1]) + (c[1] + d[1]);
    o.z = (a[2] + b[2]) + (c[2] + d[2]);
    o.w = (a[3] + b[3]) + (c[3] + d[3]);

    float4* outv = (float4*)(out + (long long)bc * (H * W) + oh * W);
    outv[q] = o;
}

extern "C" void kernel_launch(void* const* d_in, const int* in_sizes, int n_in,
                              void* d_out, int out_size) {
    const float* x = (const float*)d_in[0];
    float* out = (float*)d_out;
    int threads = 256;
    int blocks = TOTAL_Q / threads;  // 16,900 exactly
    fold_quad_l2_kernel<<<blocks, threads>>>(x, out);
}